// round 2
// baseline (speedup 1.0000x reference)
#include <cuda_runtime.h>
#include <cuda_bf16.h>
#include <math.h>

// Problem constants
#define BATCH 2
#define CIN   64
#define COUT  128
#define HH    128
#define WW    128
#define HWSZ  (HH*WW)          // 16384
#define N9    9
#define K1    (CIN*9)          // 576
#define K2C   (COUT*9)         // 1152
#define K2    (K2C + CIN)      // 1216  (conv part + identity part)

// ---------------- scratch (static device globals; no allocation) -------------
__device__ float g_off[BATCH * 18 * HWSZ];          // offset maps (reused L1/L2)
__device__ float g_col[BATCH * K2 * HWSZ];          // im2col buffer (reused)
__device__ float g_h1 [BATCH * COUT * HWSZ];        // layer-1 output
__device__ float g_w1p[COUT * K1];                  // prescaled weights layer1
__device__ float g_w2p[COUT * K2];                  // prescaled weights layer2+id
__device__ float g_b1 [COUT];
__device__ float g_b2 [COUT];

// ---------------- weight prep: fold BN into weights/bias ---------------------
__global__ void prep_kernel(const float* __restrict__ dc1_w,
                            const float* __restrict__ bn1_g, const float* __restrict__ bn1_b,
                            const float* __restrict__ bn1_m, const float* __restrict__ bn1_v,
                            const float* __restrict__ dc2_w,
                            const float* __restrict__ bn2_g, const float* __restrict__ bn2_b,
                            const float* __restrict__ bn2_m, const float* __restrict__ bn2_v,
                            const float* __restrict__ id_w,  const float* __restrict__ id_b,
                            const float* __restrict__ bn3_g, const float* __restrict__ bn3_b,
                            const float* __restrict__ bn3_m, const float* __restrict__ bn3_v)
{
    int o = threadIdx.x;            // 128 threads
    if (o >= COUT) return;
    const float eps = 1e-5f;
    float s1 = bn1_g[o] * rsqrtf(bn1_v[o] + eps);
    float t1 = bn1_b[o] - bn1_m[o] * s1;
    float s2 = bn2_g[o] * rsqrtf(bn2_v[o] + eps);
    float t2 = bn2_b[o] - bn2_m[o] * s2;
    float s3 = bn3_g[o] * rsqrtf(bn3_v[o] + eps);
    float t3 = bn3_b[o] - bn3_m[o] * s3;

    g_b1[o] = t1;
    g_b2[o] = t2 + id_b[o] * s3 + t3;

    for (int k = 0; k < K1; ++k)
        g_w1p[o * K1 + k] = dc1_w[o * K1 + k] * s1;
    for (int k = 0; k < K2C; ++k)
        g_w2p[o * K2 + k] = dc2_w[o * K2C + k] * s2;
    for (int c = 0; c < CIN; ++c)
        g_w2p[o * K2 + K2C + c] = id_w[o * CIN + c] * s3;
}

// ---------------- offset conv (3x3, pad1) ------------------------------------
// One thread per (b,h,w) pixel computes all 18 offset channels.
// Weights staged in shared memory per 64-channel chunk (18*576 floats = 41.5KB).
__global__ void offset_conv_kernel(const float* __restrict__ xext, int use_h1,
                                   const float* __restrict__ ow,
                                   const float* __restrict__ ob, int C)
{
    __shared__ float ws[18 * 576];
    const float* x = use_h1 ? g_h1 : xext;
    int b = blockIdx.y, h = blockIdx.x, w = threadIdx.x;

    float acc[18];
#pragma unroll
    for (int o = 0; o < 18; ++o) acc[o] = 0.f;

    int nchunk = C / 64;
    for (int chunk = 0; chunk < nchunk; ++chunk) {
        __syncthreads();
        for (int i = threadIdx.x; i < 18 * 576; i += blockDim.x) {
            int o = i / 576, t = i % 576;
            ws[i] = ow[o * C * 9 + chunk * 576 + t];
        }
        __syncthreads();
        const float* xb = x + ((long)b * C + chunk * 64) * HWSZ;
        for (int cc = 0; cc < 64; ++cc) {
            const float* xc = xb + cc * HWSZ;
#pragma unroll
            for (int ky = 0; ky < 3; ++ky) {
                int y = h + ky - 1;
                bool vy = (unsigned)y < (unsigned)HH;
#pragma unroll
                for (int kx = 0; kx < 3; ++kx) {
                    int xx = w + kx - 1;
                    float xv = (vy && (unsigned)xx < (unsigned)WW) ? xc[y * WW + xx] : 0.f;
                    int widx = cc * 9 + ky * 3 + kx;
#pragma unroll
                    for (int o = 0; o < 18; ++o)
                        acc[o] += ws[o * 576 + widx] * xv;
                }
            }
        }
    }
    int base = (b * 18) * HWSZ + h * WW + w;
#pragma unroll
    for (int o = 0; o < 18; ++o)
        g_off[base + o * HWSZ] = acc[o] + ob[o];
}

// ---------------- deformable bilinear sampling -> im2col ---------------------
// grid (H, 9, B), block W. Each thread handles one (b,n,h,w) for all C channels.
__global__ void deform_sample_kernel(const float* __restrict__ xext, int use_h1,
                                     int C, int Kstride)
{
    const float* xin = use_h1 ? g_h1 : xext;
    int b = blockIdx.z, n = blockIdx.y, h = blockIdx.x, w = threadIdx.x;
    int pix = h * WW + w;

    float offy = g_off[(b * 18 + n)     * HWSZ + pix];
    float offx = g_off[(b * 18 + 9 + n) * HWSZ + pix];

    float py = offy + (float)(n / 3 - 1) + (float)(h + 1);
    float px = offx + (float)(n % 3 - 1) + (float)(w + 1);
    const float hi = (float)(HH + 1);    // Hp-1 = 129
    py = fminf(fmaxf(py, 0.f), hi);
    px = fminf(fmaxf(px, 0.f), hi);

    float fy = floorf(py), fx = floorf(px);
    float qy0 = fy, qx0 = fx;
    float qy1 = fminf(fy + 1.f, hi);
    float qx1 = fminf(fx + 1.f, hi);

    float dy0 = 1.f + (qy0 - py);
    float dy1 = 1.f - (qy1 - py);
    float dx0 = 1.f + (qx0 - px);
    float dx1 = 1.f - (qx1 - px);
    float w00 = dy0 * dx0, w11 = dy1 * dx1, w01 = dy0 * dx1, w10 = dy1 * dx0;

    // padded coords -> unpadded indices
    int iy0 = (int)qy0 - 1, ix0 = (int)qx0 - 1;
    int iy1 = (int)qy1 - 1, ix1 = (int)qx1 - 1;
    bool vy0 = (unsigned)iy0 < (unsigned)HH, vy1 = (unsigned)iy1 < (unsigned)HH;
    bool vx0 = (unsigned)ix0 < (unsigned)WW, vx1 = (unsigned)ix1 < (unsigned)WW;
    bool b00 = vy0 && vx0, b11 = vy1 && vx1, b01 = vy0 && vx1, b10 = vy1 && vx0;
    int i00 = iy0 * WW + ix0, i11 = iy1 * WW + ix1;
    int i01 = iy0 * WW + ix1, i10 = iy1 * WW + ix0;

    const float* xb = xin + (long)b * C * HWSZ;
    float* cb = g_col + (long)b * Kstride * HWSZ + (long)n * HWSZ + pix;
    for (int c = 0; c < C; ++c) {
        const float* xc = xb + (long)c * HWSZ;
        float v = 0.f;
        if (b00) v += w00 * xc[i00];
        if (b11) v += w11 * xc[i11];
        if (b01) v += w01 * xc[i01];
        if (b10) v += w10 * xc[i10];
        cb[(long)c * 9 * HWSZ] = v;
    }
}

// ---------------- copy x channels into tail of col2 (identity path K rows) ---
__global__ void copy_x_tail_kernel(const float* __restrict__ x)
{
    long idx = (long)blockIdx.x * blockDim.x + threadIdx.x;
    const long total = (long)BATCH * CIN * HWSZ;
    if (idx >= total) return;
    long b = idx / ((long)CIN * HWSZ);
    long r = idx - b * (long)CIN * HWSZ;
    g_col[b * (long)K2 * HWSZ + (long)K2C * HWSZ + r] = x[idx];
}

// ---------------- GEMM: out[b][o][j] = relu(sum_k A[o][k]*col[b][k][j]+bias) -
// 128(M) x 128(N) tile, BK=16, 256 threads, 8x8 per thread.
__global__ __launch_bounds__(256)
void gemm_bias_relu_kernel(int sel, float* __restrict__ dout)
{
    const float* A    = sel ? g_w2p : g_w1p;
    const float* bias = sel ? g_b2  : g_b1;
    float* C          = sel ? dout  : g_h1;
    const int K       = sel ? K2    : K1;

    __shared__ float As[16][132];
    __shared__ float Bs[16][128];

    int b  = blockIdx.y;
    int j0 = blockIdx.x * 128;
    int tid = threadIdx.x;
    int tx = tid % 16, ty = tid / 16;

    const float* Bbase = g_col + (long)b * K * HWSZ + j0;

    float acc[8][8];
#pragma unroll
    for (int i = 0; i < 8; ++i)
#pragma unroll
        for (int j = 0; j < 8; ++j) acc[i][j] = 0.f;

    int kldA = tid % 16;       // k within tile for A-load
    int mldA = tid / 16;       // m base (16 rows/pass, 8 passes)
    int jldB = tid % 128;      // j for B-load
    int kldB = tid / 128;      // 0..1 (2 k rows/pass, 8 passes)

    for (int k0 = 0; k0 < K; k0 += 16) {
#pragma unroll
        for (int i = 0; i < 8; ++i) {
            int m = mldA + i * 16;
            As[kldA][m] = A[(long)m * K + k0 + kldA];
        }
#pragma unroll
        for (int i = 0; i < 8; ++i) {
            int kk = kldB + i * 2;
            Bs[kk][jldB] = Bbase[(long)(k0 + kk) * HWSZ + jldB];
        }
        __syncthreads();
#pragma unroll
        for (int kk = 0; kk < 16; ++kk) {
            float a[8], bb[8];
#pragma unroll
            for (int i = 0; i < 8; ++i) a[i] = As[kk][ty * 8 + i];
#pragma unroll
            for (int j = 0; j < 8; ++j) bb[j] = Bs[kk][tx * 8 + j];
#pragma unroll
            for (int i = 0; i < 8; ++i)
#pragma unroll
                for (int j = 0; j < 8; ++j)
                    acc[i][j] += a[i] * bb[j];
        }
        __syncthreads();
    }

#pragma unroll
    for (int i = 0; i < 8; ++i) {
        int m = ty * 8 + i;
        float bs = bias[m];
        float* crow = C + (long)b * COUT * HWSZ + (long)m * HWSZ + j0 + tx * 8;
#pragma unroll
        for (int j = 0; j < 8; ++j) {
            float v = acc[i][j] + bs;
            crow[j] = fmaxf(v, 0.f);
        }
    }
}

// ---------------- launch -----------------------------------------------------
extern "C" void kernel_launch(void* const* d_in, const int* in_sizes, int n_in,
                              void* d_out, int out_size)
{
    const float* x        = (const float*)d_in[0];
    const float* dc1_offw = (const float*)d_in[1];
    const float* dc1_offb = (const float*)d_in[2];
    const float* dc1_w    = (const float*)d_in[3];
    const float* bn1_g    = (const float*)d_in[4];
    const float* bn1_b    = (const float*)d_in[5];
    const float* bn1_m    = (const float*)d_in[6];
    const float* bn1_v    = (const float*)d_in[7];
    const float* dc2_offw = (const float*)d_in[8];
    const float* dc2_offb = (const float*)d_in[9];
    const float* dc2_w    = (const float*)d_in[10];
    const float* bn2_g    = (const float*)d_in[11];
    const float* bn2_b    = (const float*)d_in[12];
    const float* bn2_m    = (const float*)d_in[13];
    const float* bn2_v    = (const float*)d_in[14];
    const float* id_w     = (const float*)d_in[15];
    const float* id_b     = (const float*)d_in[16];
    const float* bn3_g    = (const float*)d_in[17];
    const float* bn3_b    = (const float*)d_in[18];
    const float* bn3_m    = (const float*)d_in[19];
    const float* bn3_v    = (const float*)d_in[20];
    float* out = (float*)d_out;

    // 0) fold BN into weights/bias
    prep_kernel<<<1, 128>>>(dc1_w, bn1_g, bn1_b, bn1_m, bn1_v,
                            dc2_w, bn2_g, bn2_b, bn2_m, bn2_v,
                            id_w, id_b, bn3_g, bn3_b, bn3_m, bn3_v);

    // 1) offsets layer 1
    offset_conv_kernel<<<dim3(HH, BATCH), WW>>>(x, 0, dc1_offw, dc1_offb, CIN);
    // 2) sample layer 1 -> col (K stride 576)
    deform_sample_kernel<<<dim3(HH, N9, BATCH), WW>>>(x, 0, CIN, K1);
    // 3) GEMM1 + bn1 + relu -> g_h1
    gemm_bias_relu_kernel<<<dim3(HWSZ / 128, BATCH), 256>>>(0, out);

    // 4) offsets layer 2 (input = g_h1)
    offset_conv_kernel<<<dim3(HH, BATCH), WW>>>(x, 1, dc2_offw, dc2_offb, COUT);
    // 5) sample layer 2 -> col rows [0,1152)
    deform_sample_kernel<<<dim3(HH, N9, BATCH), WW>>>(x, 1, COUT, K2);
    // 6) identity: x channels -> col rows [1152,1216)
    {
        long total = (long)BATCH * CIN * HWSZ;
        int threads = 256;
        int blocks = (int)((total + threads - 1) / threads);
        copy_x_tail_kernel<<<blocks, threads>>>(x);
    }
    // 7) GEMM2 (+identity) + bn2/bn3 + relu -> d_out
    gemm_bias_relu_kernel<<<dim3(HWSZ / 128, BATCH), 256>>>(1, out);
}

// round 4
// speedup vs baseline: 1.7126x; 1.7126x over previous
#include <cuda_runtime.h>
#include <cuda_bf16.h>
#include <math.h>

#define BATCH 2
#define CIN   64
#define COUT  128
#define HH    128
#define WW    128
#define HWSZ  (HH*WW)          // 16384
#define K1    576              // 9*64
#define K2C   1152             // 9*128
#define K2    1216             // + 64 identity rows

// ---------------- scratch (static device globals) ----------------------------
__device__ float g_off[BATCH * 18 * HWSZ];
__device__ __nv_bfloat16 g_colh[(long)BATCH * HWSZ * K2];   // ~80MB
__device__ __nv_bfloat16 g_coll[(long)BATCH * HWSZ * K2];   // ~80MB
__device__ float g_h1 [BATCH * COUT * HWSZ];
__device__ __nv_bfloat16 g_w1h[COUT * K1], g_w1l[COUT * K1];
__device__ __nv_bfloat16 g_w2h[COUT * K2], g_w2l[COUT * K2];
__device__ float g_b1[COUT], g_b2[COUT];
__device__ float g_s1[COUT], g_s2[COUT], g_s3[COUT];

// ---------------- PTX helpers (sm_80-era only; compute_103-safe) -------------
__device__ __forceinline__ unsigned smem_u32(const void* p) {
    unsigned a;
    asm("{ .reg .u64 t; cvta.to.shared.u64 t, %1; cvt.u32.u64 %0, t; }"
        : "=r"(a) : "l"(p));
    return a;
}
__device__ __forceinline__ void cp16(unsigned dst, const void* src) {
    asm volatile("cp.async.cg.shared.global [%0], [%1], 16;"
                 :: "r"(dst), "l"(src) : "memory");
}
__device__ __forceinline__ void cp_commit() {
    asm volatile("cp.async.commit_group;" ::: "memory");
}
__device__ __forceinline__ void cp_wait0() {
    asm volatile("cp.async.wait_group 0;" ::: "memory");
}
__device__ __forceinline__ void ldm_x4(unsigned a, unsigned r[4]) {
    asm volatile("ldmatrix.sync.aligned.m8n8.x4.shared.b16 {%0,%1,%2,%3}, [%4];"
                 : "=r"(r[0]), "=r"(r[1]), "=r"(r[2]), "=r"(r[3]) : "r"(a));
}
__device__ __forceinline__ void mma16816(float d[4], const unsigned a[4],
                                         unsigned b0, unsigned b1) {
    asm volatile(
        "mma.sync.aligned.m16n8k16.row.col.f32.bf16.bf16.f32 "
        "{%0,%1,%2,%3}, {%4,%5,%6,%7}, {%8,%9}, {%0,%1,%2,%3};"
        : "+f"(d[0]), "+f"(d[1]), "+f"(d[2]), "+f"(d[3])
        : "r"(a[0]), "r"(a[1]), "r"(a[2]), "r"(a[3]), "r"(b0), "r"(b1));
}

// ---------------- weight prep ------------------------------------------------
__global__ void prep_scales(const float* __restrict__ bn1_g, const float* __restrict__ bn1_b,
                            const float* __restrict__ bn1_m, const float* __restrict__ bn1_v,
                            const float* __restrict__ bn2_g, const float* __restrict__ bn2_b,
                            const float* __restrict__ bn2_m, const float* __restrict__ bn2_v,
                            const float* __restrict__ id_b,
                            const float* __restrict__ bn3_g, const float* __restrict__ bn3_b,
                            const float* __restrict__ bn3_m, const float* __restrict__ bn3_v)
{
    int o = threadIdx.x;
    if (o >= COUT) return;
    const float eps = 1e-5f;
    float s1 = bn1_g[o] * rsqrtf(bn1_v[o] + eps);
    float s2 = bn2_g[o] * rsqrtf(bn2_v[o] + eps);
    float s3 = bn3_g[o] * rsqrtf(bn3_v[o] + eps);
    g_s1[o] = s1; g_s2[o] = s2; g_s3[o] = s3;
    g_b1[o] = bn1_b[o] - bn1_m[o] * s1;
    g_b2[o] = (bn2_b[o] - bn2_m[o] * s2) + id_b[o] * s3 + (bn3_b[o] - bn3_m[o] * s3);
}

__device__ __forceinline__ void split_store(__nv_bfloat16* hd, __nv_bfloat16* ld,
                                            long i, float v) {
    __nv_bfloat16 h = __float2bfloat16(v);
    hd[i] = h;
    ld[i] = __float2bfloat16(v - __bfloat162float(h));
}

__global__ void prep_weights(const float* __restrict__ dc1_w,
                             const float* __restrict__ dc2_w,
                             const float* __restrict__ id_w)
{
    int idx = blockIdx.x * blockDim.x + threadIdx.x;
    const int n1 = COUT * K1, n2 = COUT * K2C, n3 = COUT * CIN;
    if (idx < n1) {
        int o = idx / K1, kk = idx % K1;
        int c = kk / 9, n = kk % 9;
        float v = dc1_w[idx] * g_s1[o];
        split_store(g_w1h, g_w1l, (long)o * K1 + n * CIN + c, v);
    } else if (idx < n1 + n2) {
        int r = idx - n1;
        int o = r / K2C, kk = r % K2C;
        int c = kk / 9, n = kk % 9;
        float v = dc2_w[r] * g_s2[o];
        split_store(g_w2h, g_w2l, (long)o * K2 + n * COUT + c, v);
    } else if (idx < n1 + n2 + n3) {
        int r = idx - n1 - n2;
        int o = r / CIN, c = r % CIN;
        float v = id_w[r] * g_s3[o];
        split_store(g_w2h, g_w2l, (long)o * K2 + K2C + c, v);
    }
}

// ---------------- offset conv (3x3, pad1) ------------------------------------
__global__ void offset_conv_kernel(const float* __restrict__ xext, int use_h1,
                                   const float* __restrict__ ow,
                                   const float* __restrict__ ob, int C)
{
    __shared__ float ws[18 * 576];
    const float* x = use_h1 ? g_h1 : xext;
    int b = blockIdx.y, h = blockIdx.x, w = threadIdx.x;

    float acc[18];
#pragma unroll
    for (int o = 0; o < 18; ++o) acc[o] = 0.f;

    int nchunk = C / 64;
    for (int chunk = 0; chunk < nchunk; ++chunk) {
        __syncthreads();
        for (int i = threadIdx.x; i < 18 * 576; i += blockDim.x) {
            int o = i / 576, t = i % 576;
            ws[i] = ow[o * C * 9 + chunk * 576 + t];
        }
        __syncthreads();
        const float* xb = x + ((long)b * C + chunk * 64) * HWSZ;
        for (int cc = 0; cc < 64; ++cc) {
            const float* xc = xb + cc * HWSZ;
#pragma unroll
            for (int ky = 0; ky < 3; ++ky) {
                int y = h + ky - 1;
                bool vy = (unsigned)y < (unsigned)HH;
#pragma unroll
                for (int kx = 0; kx < 3; ++kx) {
                    int xx = w + kx - 1;
                    float xv = (vy && (unsigned)xx < (unsigned)WW) ? xc[y * WW + xx] : 0.f;
                    int widx = cc * 9 + ky * 3 + kx;
#pragma unroll
                    for (int o = 0; o < 18; ++o)
                        acc[o] += ws[o * 576 + widx] * xv;
                }
            }
        }
    }
    int base = (b * 18) * HWSZ + h * WW + w;
#pragma unroll
    for (int o = 0; o < 18; ++o)
        g_off[base + o * HWSZ] = acc[o] + ob[o];
}

// ---------------- deformable sampling -> bf16 hi/lo col (pixel-major K) ------
template<int C, int KP>
__global__ void deform_sample_kernel(const float* __restrict__ xext, int use_h1)
{
    const float* xin = use_h1 ? g_h1 : xext;
    int b = blockIdx.z, n = blockIdx.y, h = blockIdx.x, w = threadIdx.x;
    int pix = h * WW + w;

    float offy = g_off[(b * 18 + n)     * HWSZ + pix];
    float offx = g_off[(b * 18 + 9 + n) * HWSZ + pix];
    float py = offy + (float)(n / 3 - 1) + (float)(h + 1);
    float px = offx + (float)(n % 3 - 1) + (float)(w + 1);
    const float hiB = 129.f;   // Hp-1
    py = fminf(fmaxf(py, 0.f), hiB);
    px = fminf(fmaxf(px, 0.f), hiB);
    float fy = floorf(py), fx = floorf(px);
    float qy1 = fminf(fy + 1.f, hiB), qx1 = fminf(fx + 1.f, hiB);
    float dy0 = 1.f + (fy - py), dy1 = 1.f - (qy1 - py);
    float dx0 = 1.f + (fx - px), dx1 = 1.f - (qx1 - px);
    int iy0 = (int)fy - 1, ix0 = (int)fx - 1;
    int iy1 = (int)qy1 - 1, ix1 = (int)qx1 - 1;
    bool vy0 = (unsigned)iy0 < (unsigned)HH, vy1 = (unsigned)iy1 < (unsigned)HH;
    bool vx0 = (unsigned)ix0 < (unsigned)WW, vx1 = (unsigned)ix1 < (unsigned)WW;
    float w00 = (vy0 && vx0) ? dy0 * dx0 : 0.f;
    float w01 = (vy0 && vx1) ? dy0 * dx1 : 0.f;
    float w10 = (vy1 && vx0) ? dy1 * dx0 : 0.f;
    float w11 = (vy1 && vx1) ? dy1 * dx1 : 0.f;
    int cy0 = min(max(iy0, 0), HH - 1), cy1 = min(max(iy1, 0), HH - 1);
    int cx0 = min(max(ix0, 0), WW - 1), cx1 = min(max(ix1, 0), WW - 1);
    int j00 = cy0 * WW + cx0, j01 = cy0 * WW + cx1;
    int j10 = cy1 * WW + cx0, j11 = cy1 * WW + cx1;

    const float* xb = xin + (long)b * C * HWSZ;
    long row = ((long)b * HWSZ + pix) * KP + (long)n * C;
    __nv_bfloat16* dh = g_colh + row;
    __nv_bfloat16* dl = g_coll + row;

    for (int c0 = 0; c0 < C; c0 += 8) {
        unsigned hv[4], lv[4];
#pragma unroll
        for (int u = 0; u < 4; ++u) {
            const float* xc0 = xb + (long)(c0 + 2 * u) * HWSZ;
            const float* xc1 = xc0 + HWSZ;
            float v0 = w00 * xc0[j00] + w01 * xc0[j01] + w10 * xc0[j10] + w11 * xc0[j11];
            float v1 = w00 * xc1[j00] + w01 * xc1[j01] + w10 * xc1[j10] + w11 * xc1[j11];
            __nv_bfloat16 h0 = __float2bfloat16(v0), h1 = __float2bfloat16(v1);
            __nv_bfloat16 l0 = __float2bfloat16(v0 - __bfloat162float(h0));
            __nv_bfloat16 l1 = __float2bfloat16(v1 - __bfloat162float(h1));
            hv[u] = (unsigned)__bfloat16_as_ushort(h0) | ((unsigned)__bfloat16_as_ushort(h1) << 16);
            lv[u] = (unsigned)__bfloat16_as_ushort(l0) | ((unsigned)__bfloat16_as_ushort(l1) << 16);
        }
        *(uint4*)(dh + c0) = make_uint4(hv[0], hv[1], hv[2], hv[3]);
        *(uint4*)(dl + c0) = make_uint4(lv[0], lv[1], lv[2], lv[3]);
    }
}

// ---------------- identity: x channels -> col2 tail rows ---------------------
__global__ void copy_x_tail_kernel(const float* __restrict__ x)
{
    int b = blockIdx.y;
    int pix = blockIdx.x * 128 + threadIdx.x;
    const float* xb = x + (long)b * CIN * HWSZ;
    long row = ((long)b * HWSZ + pix) * K2 + K2C;
    __nv_bfloat16* dh = g_colh + row;
    __nv_bfloat16* dl = g_coll + row;
    for (int c0 = 0; c0 < CIN; c0 += 8) {
        unsigned hv[4], lv[4];
#pragma unroll
        for (int u = 0; u < 4; ++u) {
            float v0 = xb[(long)(c0 + 2 * u) * HWSZ + pix];
            float v1 = xb[(long)(c0 + 2 * u + 1) * HWSZ + pix];
            __nv_bfloat16 h0 = __float2bfloat16(v0), h1 = __float2bfloat16(v1);
            __nv_bfloat16 l0 = __float2bfloat16(v0 - __bfloat162float(h0));
            __nv_bfloat16 l1 = __float2bfloat16(v1 - __bfloat162float(h1));
            hv[u] = (unsigned)__bfloat16_as_ushort(h0) | ((unsigned)__bfloat16_as_ushort(h1) << 16);
            lv[u] = (unsigned)__bfloat16_as_ushort(l0) | ((unsigned)__bfloat16_as_ushort(l1) << 16);
        }
        *(uint4*)(dh + c0) = make_uint4(hv[0], hv[1], hv[2], hv[3]);
        *(uint4*)(dl + c0) = make_uint4(lv[0], lv[1], lv[2], lv[3]);
    }
}

// ---------------- HMMA bf16x3 GEMM + bias + relu -----------------------------
// out[o][j] = relu(sum_k W[o][k]*col[j][k] + bias[o]); M=128, N=128/CTA, BK=32
// smem buffer: 4 matrices (Ah, Al, Bh, Bl), 128 rows x 40 bf16 (80B padded rows)
#define ROWB 80
#define MAT_BYTES (128 * ROWB)        // 10240
#define BUF_BYTES (4 * MAT_BYTES)     // 40960
#define GEMM_SMEM (2 * BUF_BYTES)     // 81920

__global__ __launch_bounds__(256)
void gemm_mma_kernel(int sel, float* __restrict__ dout)
{
    extern __shared__ char sm[];
    const __nv_bfloat16* Ah = sel ? g_w2h : g_w1h;
    const __nv_bfloat16* Al = sel ? g_w2l : g_w1l;
    const float* bias       = sel ? g_b2  : g_b1;
    float* Cp               = sel ? dout  : g_h1;
    const int K             = sel ? K2    : K1;

    const int tid = threadIdx.x;
    const int warp = tid >> 5, lane = tid & 31;
    const int mbase = (warp >> 2) * 64;       // 2 warp-rows
    const int nbase = (warp & 3) * 32;        // 4 warp-cols
    const int b = blockIdx.y, j0 = blockIdx.x * 128;
    const unsigned sb = smem_u32(sm);

    // global source rows for cp.async (2 segs of 16B per thread per matrix)
    const int r0 = (tid + 0)   >> 2, s0 = (tid + 0)   & 3;
    const int r1 = (tid + 256) >> 2, s1 = (tid + 256) & 3;
    const long jrow0 = ((long)b * HWSZ + j0 + r0) * K;
    const long jrow1 = ((long)b * HWSZ + j0 + r1) * K;

    float d[16][4];
#pragma unroll
    for (int i = 0; i < 16; ++i)
#pragma unroll
        for (int j = 0; j < 4; ++j) d[i][j] = 0.f;

    // ldmatrix smem addresses (per k-chunk buffer base added later)
    // A: row = mbase + mt*16 + (lane&15); k-16B-half = (lane>>4)&1
    const unsigned a_row = (unsigned)(mbase + (lane & 15));
    const unsigned a_kh  = (unsigned)((lane >> 4) & 1) * 16u;
    // B: row = nbase + ntp*16 + (lane&7) + ((lane>>4)&1)*8 ; k-half = (lane>>3)&1
    const unsigned b_row = (unsigned)(nbase + (lane & 7) + (((lane >> 4) & 1) << 3));
    const unsigned b_kh  = (unsigned)((lane >> 3) & 1) * 16u;

    int nchunk = K / 32;
    unsigned p = 0;

    // prologue: load chunk 0
    {
        int k0 = 0;
        unsigned dst0 = sb + r0 * ROWB + s0 * 16;
        unsigned dst1 = sb + r1 * ROWB + s1 * 16;
        cp16(dst0,                 Ah + (long)r0 * K + k0 + s0 * 8);
        cp16(dst0 + MAT_BYTES,     Al + (long)r0 * K + k0 + s0 * 8);
        cp16(dst0 + 2 * MAT_BYTES, g_colh + jrow0 + k0 + s0 * 8);
        cp16(dst0 + 3 * MAT_BYTES, g_coll + jrow0 + k0 + s0 * 8);
        cp16(dst1,                 Ah + (long)r1 * K + k0 + s1 * 8);
        cp16(dst1 + MAT_BYTES,     Al + (long)r1 * K + k0 + s1 * 8);
        cp16(dst1 + 2 * MAT_BYTES, g_colh + jrow1 + k0 + s1 * 8);
        cp16(dst1 + 3 * MAT_BYTES, g_coll + jrow1 + k0 + s1 * 8);
        cp_commit();
    }

    for (int ch = 0; ch < nchunk; ++ch) {
        cp_wait0();
        __syncthreads();

        if (ch + 1 < nchunk) {
            int k0 = (ch + 1) * 32;
            unsigned bb = sb + (p ^ 1) * BUF_BYTES;
            unsigned dst0 = bb + r0 * ROWB + s0 * 16;
            unsigned dst1 = bb + r1 * ROWB + s1 * 16;
            cp16(dst0,                 Ah + (long)r0 * K + k0 + s0 * 8);
            cp16(dst0 + MAT_BYTES,     Al + (long)r0 * K + k0 + s0 * 8);
            cp16(dst0 + 2 * MAT_BYTES, g_colh + jrow0 + k0 + s0 * 8);
            cp16(dst0 + 3 * MAT_BYTES, g_coll + jrow0 + k0 + s0 * 8);
            cp16(dst1,                 Ah + (long)r1 * K + k0 + s1 * 8);
            cp16(dst1 + MAT_BYTES,     Al + (long)r1 * K + k0 + s1 * 8);
            cp16(dst1 + 2 * MAT_BYTES, g_colh + jrow1 + k0 + s1 * 8);
            cp16(dst1 + 3 * MAT_BYTES, g_coll + jrow1 + k0 + s1 * 8);
            cp_commit();
        }

        unsigned bufA = sb + p * BUF_BYTES;
#pragma unroll
        for (int kk = 0; kk < 2; ++kk) {
            unsigned ah[4][4], al[4][4], bh[2][4], bl[2][4];
#pragma unroll
            for (int mt = 0; mt < 4; ++mt) {
                unsigned addr = bufA + (a_row + mt * 16u) * ROWB + a_kh + kk * 32u;
                ldm_x4(addr, ah[mt]);
                ldm_x4(addr + MAT_BYTES, al[mt]);
            }
#pragma unroll
            for (int np = 0; np < 2; ++np) {
                unsigned addr = bufA + 2 * MAT_BYTES +
                                (b_row + np * 16u) * ROWB + b_kh + kk * 32u;
                ldm_x4(addr, bh[np]);
                ldm_x4(addr + MAT_BYTES, bl[np]);
            }
#pragma unroll
            for (int mt = 0; mt < 4; ++mt) {
#pragma unroll
                for (int nt = 0; nt < 4; ++nt) {
                    int np = nt >> 1, rp = (nt & 1) * 2;
                    float* acc = d[mt * 4 + nt];
                    mma16816(acc, ah[mt], bh[np][rp], bh[np][rp + 1]);
                    mma16816(acc, ah[mt], bl[np][rp], bl[np][rp + 1]);
                    mma16816(acc, al[mt], bh[np][rp], bh[np][rp + 1]);
                }
            }
        }
        __syncthreads();
        p ^= 1;
    }

    // epilogue: bias + relu, float2 stores
    const int qr = lane >> 2;          // 0..7
    const int qc = (lane & 3) * 2;     // 0,2,4,6
#pragma unroll
    for (int mt = 0; mt < 4; ++mt) {
        int o0 = mbase + mt * 16 + qr;
        int o1 = o0 + 8;
        float bs0 = bias[o0], bs1 = bias[o1];
        float* row0 = Cp + ((long)b * COUT + o0) * HWSZ + j0 + nbase + qc;
        float* row1 = Cp + ((long)b * COUT + o1) * HWSZ + j0 + nbase + qc;
#pragma unroll
        for (int nt = 0; nt < 4; ++nt) {
            float* acc = d[mt * 4 + nt];
            float2 v0 = make_float2(fmaxf(acc[0] + bs0, 0.f), fmaxf(acc[1] + bs0, 0.f));
            float2 v1 = make_float2(fmaxf(acc[2] + bs1, 0.f), fmaxf(acc[3] + bs1, 0.f));
            *(float2*)(row0 + nt * 8) = v0;
            *(float2*)(row1 + nt * 8) = v1;
        }
    }
}

// ---------------- launch -----------------------------------------------------
extern "C" void kernel_launch(void* const* d_in, const int* in_sizes, int n_in,
                              void* d_out, int out_size)
{
    const float* x        = (const float*)d_in[0];
    const float* dc1_offw = (const float*)d_in[1];
    const float* dc1_offb = (const float*)d_in[2];
    const float* dc1_w    = (const float*)d_in[3];
    const float* bn1_g    = (const float*)d_in[4];
    const float* bn1_b    = (const float*)d_in[5];
    const float* bn1_m    = (const float*)d_in[6];
    const float* bn1_v    = (const float*)d_in[7];
    const float* dc2_offw = (const float*)d_in[8];
    const float* dc2_offb = (const float*)d_in[9];
    const float* dc2_w    = (const float*)d_in[10];
    const float* bn2_g    = (const float*)d_in[11];
    const float* bn2_b    = (const float*)d_in[12];
    const float* bn2_m    = (const float*)d_in[13];
    const float* bn2_v    = (const float*)d_in[14];
    const float* id_w     = (const float*)d_in[15];
    const float* id_b     = (const float*)d_in[16];
    const float* bn3_g    = (const float*)d_in[17];
    const float* bn3_b    = (const float*)d_in[18];
    const float* bn3_m    = (const float*)d_in[19];
    const float* bn3_v    = (const float*)d_in[20];
    float* out = (float*)d_out;

    cudaFuncSetAttribute(gemm_mma_kernel,
                         cudaFuncAttributeMaxDynamicSharedMemorySize, GEMM_SMEM);

    prep_scales<<<1, 128>>>(bn1_g, bn1_b, bn1_m, bn1_v,
                            bn2_g, bn2_b, bn2_m, bn2_v,
                            id_b, bn3_g, bn3_b, bn3_m, bn3_v);
    {
        int total = COUT * K1 + COUT * K2C + COUT * CIN;
        prep_weights<<<(total + 255) / 256, 256>>>(dc1_w, dc2_w, id_w);
    }

    offset_conv_kernel<<<dim3(HH, BATCH), WW>>>(x, 0, dc1_offw, dc1_offb, CIN);
    deform_sample_kernel<CIN, K1><<<dim3(HH, 9, BATCH), WW>>>(x, 0);
    gemm_mma_kernel<<<dim3(HWSZ / 128, BATCH), 256, GEMM_SMEM>>>(0, out);

    offset_conv_kernel<<<dim3(HH, BATCH), WW>>>(x, 1, dc2_offw, dc2_offb, COUT);
    deform_sample_kernel<COUT, K2><<<dim3(HH, 9, BATCH), WW>>>(x, 1);
    copy_x_tail_kernel<<<dim3(HWSZ / 128, BATCH), 128>>>(x);
    gemm_mma_kernel<<<dim3(HWSZ / 128, BATCH), 256, GEMM_SMEM>>>(1, out);
}

// round 5
// speedup vs baseline: 2.8018x; 1.6359x over previous
#include <cuda_runtime.h>
#include <cuda_bf16.h>
#include <math.h>

#define BATCH 2
#define CIN   64
#define COUT  128
#define HH    128
#define WW    128
#define HWSZ  (HH*WW)          // 16384
#define K1    576              // 9*64
#define K2C   1152             // 9*128
#define K2    1216             // + 64 identity rows

// ---------------- scratch (static device globals) ----------------------------
__device__ float g_off[BATCH * 18 * HWSZ];
__device__ float g_offp[8 * BATCH * 18 * HWSZ];             // per-chunk partials
__device__ __nv_bfloat16 g_colh[(long)BATCH * HWSZ * K2];   // ~80MB
__device__ __nv_bfloat16 g_coll[(long)BATCH * HWSZ * K2];   // ~80MB
__device__ float g_h1 [BATCH * COUT * HWSZ];
__device__ __nv_bfloat16 g_w1h[COUT * K1], g_w1l[COUT * K1];
__device__ __nv_bfloat16 g_w2h[COUT * K2], g_w2l[COUT * K2];
__device__ float g_b1[COUT], g_b2[COUT];
__device__ float g_s1[COUT], g_s2[COUT], g_s3[COUT];

// ---------------- PTX helpers (sm_80-era only; compute_103-safe) -------------
__device__ __forceinline__ unsigned smem_u32(const void* p) {
    unsigned a;
    asm("{ .reg .u64 t; cvta.to.shared.u64 t, %1; cvt.u32.u64 %0, t; }"
        : "=r"(a) : "l"(p));
    return a;
}
__device__ __forceinline__ void cp16(unsigned dst, const void* src) {
    asm volatile("cp.async.cg.shared.global [%0], [%1], 16;"
                 :: "r"(dst), "l"(src) : "memory");
}
__device__ __forceinline__ void cp_commit() {
    asm volatile("cp.async.commit_group;" ::: "memory");
}
__device__ __forceinline__ void cp_wait0() {
    asm volatile("cp.async.wait_group 0;" ::: "memory");
}
__device__ __forceinline__ void ldm_x4(unsigned a, unsigned r[4]) {
    asm volatile("ldmatrix.sync.aligned.m8n8.x4.shared.b16 {%0,%1,%2,%3}, [%4];"
                 : "=r"(r[0]), "=r"(r[1]), "=r"(r[2]), "=r"(r[3]) : "r"(a));
}
__device__ __forceinline__ void mma16816(float d[4], const unsigned a[4],
                                         unsigned b0, unsigned b1) {
    asm volatile(
        "mma.sync.aligned.m16n8k16.row.col.f32.bf16.bf16.f32 "
        "{%0,%1,%2,%3}, {%4,%5,%6,%7}, {%8,%9}, {%0,%1,%2,%3};"
        : "+f"(d[0]), "+f"(d[1]), "+f"(d[2]), "+f"(d[3])
        : "r"(a[0]), "r"(a[1]), "r"(a[2]), "r"(a[3]), "r"(b0), "r"(b1));
}

// ---------------- weight prep ------------------------------------------------
__global__ void prep_scales(const float* __restrict__ bn1_g, const float* __restrict__ bn1_b,
                            const float* __restrict__ bn1_m, const float* __restrict__ bn1_v,
                            const float* __restrict__ bn2_g, const float* __restrict__ bn2_b,
                            const float* __restrict__ bn2_m, const float* __restrict__ bn2_v,
                            const float* __restrict__ id_b,
                            const float* __restrict__ bn3_g, const float* __restrict__ bn3_b,
                            const float* __restrict__ bn3_m, const float* __restrict__ bn3_v)
{
    int o = threadIdx.x;
    if (o >= COUT) return;
    const float eps = 1e-5f;
    float s1 = bn1_g[o] * rsqrtf(bn1_v[o] + eps);
    float s2 = bn2_g[o] * rsqrtf(bn2_v[o] + eps);
    float s3 = bn3_g[o] * rsqrtf(bn3_v[o] + eps);
    g_s1[o] = s1; g_s2[o] = s2; g_s3[o] = s3;
    g_b1[o] = bn1_b[o] - bn1_m[o] * s1;
    g_b2[o] = (bn2_b[o] - bn2_m[o] * s2) + id_b[o] * s3 + (bn3_b[o] - bn3_m[o] * s3);
}

__device__ __forceinline__ void split_store(__nv_bfloat16* hd, __nv_bfloat16* ld,
                                            long i, float v) {
    __nv_bfloat16 h = __float2bfloat16(v);
    hd[i] = h;
    ld[i] = __float2bfloat16(v - __bfloat162float(h));
}

__global__ void prep_weights(const float* __restrict__ dc1_w,
                             const float* __restrict__ dc2_w,
                             const float* __restrict__ id_w)
{
    int idx = blockIdx.x * blockDim.x + threadIdx.x;
    const int n1 = COUT * K1, n2 = COUT * K2C, n3 = COUT * CIN;
    if (idx < n1) {
        int o = idx / K1, kk = idx % K1;
        int c = kk / 9, n = kk % 9;
        float v = dc1_w[idx] * g_s1[o];
        split_store(g_w1h, g_w1l, (long)o * K1 + n * CIN + c, v);
    } else if (idx < n1 + n2) {
        int r = idx - n1;
        int o = r / K2C, kk = r % K2C;
        int c = kk / 9, n = kk % 9;
        float v = dc2_w[r] * g_s2[o];
        split_store(g_w2h, g_w2l, (long)o * K2 + n * COUT + c, v);
    } else if (idx < n1 + n2 + n3) {
        int r = idx - n1 - n2;
        int o = r / CIN, c = r % CIN;
        float v = id_w[r] * g_s3[o];
        split_store(g_w2h, g_w2l, (long)o * K2 + K2C + c, v);
    }
}

// ---------------- offset conv: smem-tiled partial conv -----------------------
// grid (WW/16, HH/16, BATCH * C/16), block 128, 2 px/thread (rows py, py+8)
__global__ __launch_bounds__(128)
void offset_partial_kernel(const float* __restrict__ xext, int use_h1,
                           const float* __restrict__ ow, int C)
{
    __shared__ float xs[16][324];      // 16 ch x 18x18 halo tile
    __shared__ float ws[16 * 9 * 18];  // [c][tap][o]
    const float* x = use_h1 ? g_h1 : xext;
    const int CH = C / 16;
    const int z = blockIdx.z;
    const int b = z / CH, ch = z % CH, c0 = ch * 16;
    const int tx0 = blockIdx.x * 16, ty0 = blockIdx.y * 16;
    const int t = threadIdx.x;
    const int py = t >> 4, px = t & 15;

    // load weight chunk: ws[c][tap][o]
    for (int i = t; i < 16 * 162; i += 128) {
        int c = i / 162, r = i % 162, tap = r / 18, o = r % 18;
        ws[i] = ow[o * C * 9 + (c0 + c) * 9 + tap];
    }
    // load x halo tile
    for (int i = t; i < 16 * 324; i += 128) {
        int c = i / 324, rr = (i % 324) / 18, cc = i % 18;
        int gy = ty0 - 1 + rr, gx = tx0 - 1 + cc;
        float v = 0.f;
        if ((unsigned)gy < (unsigned)HH && (unsigned)gx < (unsigned)WW)
            v = x[((long)b * C + c0 + c) * HWSZ + gy * WW + gx];
        xs[c][rr * 18 + cc] = v;
    }
    __syncthreads();

    float acc[2][18];
#pragma unroll
    for (int q = 0; q < 2; ++q)
#pragma unroll
        for (int o = 0; o < 18; ++o) acc[q][o] = 0.f;

    for (int c = 0; c < 16; ++c) {
#pragma unroll
        for (int tap = 0; tap < 9; ++tap) {
            int ky = tap / 3, kx = tap % 3;
            float xv0 = xs[c][(py + ky) * 18 + px + kx];
            float xv1 = xs[c][(py + 8 + ky) * 18 + px + kx];
            const float* wrow = &ws[(c * 9 + tap) * 18];
#pragma unroll
            for (int o = 0; o < 18; ++o) {
                float w = wrow[o];
                acc[0][o] += w * xv0;
                acc[1][o] += w * xv1;
            }
        }
    }

    float* pp = g_offp + (long)ch * (BATCH * 18 * HWSZ);
#pragma unroll
    for (int q = 0; q < 2; ++q) {
        int row = ty0 + py + q * 8;
#pragma unroll
        for (int o = 0; o < 18; ++o)
            pp[((long)b * 18 + o) * HWSZ + row * WW + tx0 + px] = acc[q][o];
    }
}

__global__ void offset_reduce_kernel(const float* __restrict__ ob, int CH)
{
    int idx = blockIdx.x * blockDim.x + threadIdx.x;
    const int total = BATCH * 18 * HWSZ;
    if (idx >= total) return;
    int o = (idx / HWSZ) % 18;
    float s = ob[o];
    for (int c = 0; c < CH; ++c)
        s += g_offp[(long)c * total + idx];
    g_off[idx] = s;
}

// ---------------- deformable sampling -> bf16 hi/lo col (staged stores) ------
template<int C, int KP>
__global__ __launch_bounds__(128)
void deform_sample_kernel(const float* __restrict__ xext, int use_h1)
{
    __shared__ __nv_bfloat16 sh[128 * 64];
    __shared__ __nv_bfloat16 sl[128 * 64];
    const float* xin = use_h1 ? g_h1 : xext;
    int b = blockIdx.z, n = blockIdx.y, h = blockIdx.x, w = threadIdx.x;
    int pix = h * WW + w;

    float offy = g_off[(b * 18 + n)     * HWSZ + pix];
    float offx = g_off[(b * 18 + 9 + n) * HWSZ + pix];
    float py = offy + (float)(n / 3 - 1) + (float)(h + 1);
    float px = offx + (float)(n % 3 - 1) + (float)(w + 1);
    const float hiB = 129.f;   // Hp-1
    py = fminf(fmaxf(py, 0.f), hiB);
    px = fminf(fmaxf(px, 0.f), hiB);
    float fy = floorf(py), fx = floorf(px);
    float qy1 = fminf(fy + 1.f, hiB), qx1 = fminf(fx + 1.f, hiB);
    float dy0 = 1.f + (fy - py), dy1 = 1.f - (qy1 - py);
    float dx0 = 1.f + (fx - px), dx1 = 1.f - (qx1 - px);
    int iy0 = (int)fy - 1, ix0 = (int)fx - 1;
    int iy1 = (int)qy1 - 1, ix1 = (int)qx1 - 1;
    bool vy0 = (unsigned)iy0 < (unsigned)HH, vy1 = (unsigned)iy1 < (unsigned)HH;
    bool vx0 = (unsigned)ix0 < (unsigned)WW, vx1 = (unsigned)ix1 < (unsigned)WW;
    float w00 = (vy0 && vx0) ? dy0 * dx0 : 0.f;
    float w01 = (vy0 && vx1) ? dy0 * dx1 : 0.f;
    float w10 = (vy1 && vx0) ? dy1 * dx0 : 0.f;
    float w11 = (vy1 && vx1) ? dy1 * dx1 : 0.f;
    int cy0 = min(max(iy0, 0), HH - 1), cy1 = min(max(iy1, 0), HH - 1);
    int cx0 = min(max(ix0, 0), WW - 1), cx1 = min(max(ix1, 0), WW - 1);
    int j00 = cy0 * WW + cx0, j01 = cy0 * WW + cx1;
    int j10 = cy1 * WW + cx0, j11 = cy1 * WW + cx1;

    const float* xb = xin + (long)b * C * HWSZ;
    const unsigned wsw = (unsigned)(w & 7);

    for (int cg = 0; cg < C; cg += 64) {
        for (int c0 = 0; c0 < 64; c0 += 8) {
            unsigned hv[4], lv[4];
#pragma unroll
            for (int u = 0; u < 4; ++u) {
                const float* xc0 = xb + (long)(cg + c0 + 2 * u) * HWSZ;
                const float* xc1 = xc0 + HWSZ;
                float v0 = w00 * xc0[j00] + w01 * xc0[j01] + w10 * xc0[j10] + w11 * xc0[j11];
                float v1 = w00 * xc1[j00] + w01 * xc1[j01] + w10 * xc1[j10] + w11 * xc1[j11];
                __nv_bfloat16 h0 = __float2bfloat16(v0), h1 = __float2bfloat16(v1);
                __nv_bfloat16 l0 = __float2bfloat16(v0 - __bfloat162float(h0));
                __nv_bfloat16 l1 = __float2bfloat16(v1 - __bfloat162float(h1));
                hv[u] = (unsigned)__bfloat16_as_ushort(h0) | ((unsigned)__bfloat16_as_ushort(h1) << 16);
                lv[u] = (unsigned)__bfloat16_as_ushort(l0) | ((unsigned)__bfloat16_as_ushort(l1) << 16);
            }
            unsigned slot = ((unsigned)w << 3) | ((unsigned)(c0 >> 3) ^ wsw);
            ((uint4*)sh)[slot] = make_uint4(hv[0], hv[1], hv[2], hv[3]);
            ((uint4*)sl)[slot] = make_uint4(lv[0], lv[1], lv[2], lv[3]);
        }
        __syncthreads();
        // cooperative coalesced writes: 8 lanes cover one pixel's 128B segment
        long base = ((long)b * HWSZ + h * WW) * KP + (long)n * C + cg;
#pragma unroll
        for (int i = 0; i < 8; ++i) {
            int idx = i * 128 + (int)threadIdx.x;
            int p = idx >> 3, seg = idx & 7;
            unsigned slot = ((unsigned)p << 3) | ((unsigned)seg ^ (unsigned)(p & 7));
            *(uint4*)(g_colh + base + (long)p * KP + seg * 8) = ((uint4*)sh)[slot];
            *(uint4*)(g_coll + base + (long)p * KP + seg * 8) = ((uint4*)sl)[slot];
        }
        __syncthreads();
    }
}

// ---------------- identity: x channels -> col2 tail rows (staged) ------------
__global__ __launch_bounds__(128)
void copy_x_tail_kernel(const float* __restrict__ x)
{
    __shared__ __nv_bfloat16 sh[128 * 64];
    __shared__ __nv_bfloat16 sl[128 * 64];
    int b = blockIdx.y;
    int pix0 = blockIdx.x * 128;
    int t = threadIdx.x;
    int pix = pix0 + t;
    const float* xb = x + (long)b * CIN * HWSZ;
    const unsigned wsw = (unsigned)(t & 7);

    for (int c0 = 0; c0 < CIN; c0 += 8) {
        unsigned hv[4], lv[4];
#pragma unroll
        for (int u = 0; u < 4; ++u) {
            float v0 = xb[(long)(c0 + 2 * u) * HWSZ + pix];
            float v1 = xb[(long)(c0 + 2 * u + 1) * HWSZ + pix];
            __nv_bfloat16 h0 = __float2bfloat16(v0), h1 = __float2bfloat16(v1);
            __nv_bfloat16 l0 = __float2bfloat16(v0 - __bfloat162float(h0));
            __nv_bfloat16 l1 = __float2bfloat16(v1 - __bfloat162float(h1));
            hv[u] = (unsigned)__bfloat16_as_ushort(h0) | ((unsigned)__bfloat16_as_ushort(h1) << 16);
            lv[u] = (unsigned)__bfloat16_as_ushort(l0) | ((unsigned)__bfloat16_as_ushort(l1) << 16);
        }
        unsigned slot = ((unsigned)t << 3) | ((unsigned)(c0 >> 3) ^ wsw);
        ((uint4*)sh)[slot] = make_uint4(hv[0], hv[1], hv[2], hv[3]);
        ((uint4*)sl)[slot] = make_uint4(lv[0], lv[1], lv[2], lv[3]);
    }
    __syncthreads();
    long base = ((long)b * HWSZ + pix0) * K2 + K2C;
#pragma unroll
    for (int i = 0; i < 8; ++i) {
        int idx = i * 128 + t;
        int p = idx >> 3, seg = idx & 7;
        unsigned slot = ((unsigned)p << 3) | ((unsigned)seg ^ (unsigned)(p & 7));
        *(uint4*)(g_colh + base + (long)p * K2 + seg * 8) = ((uint4*)sh)[slot];
        *(uint4*)(g_coll + base + (long)p * K2 + seg * 8) = ((uint4*)sl)[slot];
    }
}

// ---------------- HMMA bf16x3 GEMM + bias + relu -----------------------------
#define ROWB 80
#define MAT_BYTES (128 * ROWB)        // 10240
#define BUF_BYTES (4 * MAT_BYTES)     // 40960
#define GEMM_SMEM (2 * BUF_BYTES)     // 81920

__global__ __launch_bounds__(256)
void gemm_mma_kernel(int sel, float* __restrict__ dout)
{
    extern __shared__ char sm[];
    const __nv_bfloat16* Ah = sel ? g_w2h : g_w1h;
    const __nv_bfloat16* Al = sel ? g_w2l : g_w1l;
    const float* bias       = sel ? g_b2  : g_b1;
    float* Cp               = sel ? dout  : g_h1;
    const int K             = sel ? K2    : K1;

    const int tid = threadIdx.x;
    const int warp = tid >> 5, lane = tid & 31;
    const int mbase = (warp >> 2) * 64;
    const int nbase = (warp & 3) * 32;
    const int b = blockIdx.y, j0 = blockIdx.x * 128;
    const unsigned sb = smem_u32(sm);

    const int r0 = (tid + 0)   >> 2, s0 = (tid + 0)   & 3;
    const int r1 = (tid + 256) >> 2, s1 = (tid + 256) & 3;
    const long jrow0 = ((long)b * HWSZ + j0 + r0) * K;
    const long jrow1 = ((long)b * HWSZ + j0 + r1) * K;

    float d[16][4];
#pragma unroll
    for (int i = 0; i < 16; ++i)
#pragma unroll
        for (int j = 0; j < 4; ++j) d[i][j] = 0.f;

    const unsigned a_row = (unsigned)(mbase + (lane & 15));
    const unsigned a_kh  = (unsigned)((lane >> 4) & 1) * 16u;
    const unsigned b_row = (unsigned)(nbase + (lane & 7) + (((lane >> 4) & 1) << 3));
    const unsigned b_kh  = (unsigned)((lane >> 3) & 1) * 16u;

    int nchunk = K / 32;
    unsigned p = 0;

    {
        int k0 = 0;
        unsigned dst0 = sb + r0 * ROWB + s0 * 16;
        unsigned dst1 = sb + r1 * ROWB + s1 * 16;
        cp16(dst0,                 Ah + (long)r0 * K + k0 + s0 * 8);
        cp16(dst0 + MAT_BYTES,     Al + (long)r0 * K + k0 + s0 * 8);
        cp16(dst0 + 2 * MAT_BYTES, g_colh + jrow0 + k0 + s0 * 8);
        cp16(dst0 + 3 * MAT_BYTES, g_coll + jrow0 + k0 + s0 * 8);
        cp16(dst1,                 Ah + (long)r1 * K + k0 + s1 * 8);
        cp16(dst1 + MAT_BYTES,     Al + (long)r1 * K + k0 + s1 * 8);
        cp16(dst1 + 2 * MAT_BYTES, g_colh + jrow1 + k0 + s1 * 8);
        cp16(dst1 + 3 * MAT_BYTES, g_coll + jrow1 + k0 + s1 * 8);
        cp_commit();
    }

    for (int ch = 0; ch < nchunk; ++ch) {
        cp_wait0();
        __syncthreads();

        if (ch + 1 < nchunk) {
            int k0 = (ch + 1) * 32;
            unsigned bb = sb + (p ^ 1) * BUF_BYTES;
            unsigned dst0 = bb + r0 * ROWB + s0 * 16;
            unsigned dst1 = bb + r1 * ROWB + s1 * 16;
            cp16(dst0,                 Ah + (long)r0 * K + k0 + s0 * 8);
            cp16(dst0 + MAT_BYTES,     Al + (long)r0 * K + k0 + s0 * 8);
            cp16(dst0 + 2 * MAT_BYTES, g_colh + jrow0 + k0 + s0 * 8);
            cp16(dst0 + 3 * MAT_BYTES, g_coll + jrow0 + k0 + s0 * 8);
            cp16(dst1,                 Ah + (long)r1 * K + k0 + s1 * 8);
            cp16(dst1 + MAT_BYTES,     Al + (long)r1 * K + k0 + s1 * 8);
            cp16(dst1 + 2 * MAT_BYTES, g_colh + jrow1 + k0 + s1 * 8);
            cp16(dst1 + 3 * MAT_BYTES, g_coll + jrow1 + k0 + s1 * 8);
            cp_commit();
        }

        unsigned bufA = sb + p * BUF_BYTES;
#pragma unroll
        for (int kk = 0; kk < 2; ++kk) {
            unsigned ah[4][4], al[4][4], bh[2][4], bl[2][4];
#pragma unroll
            for (int mt = 0; mt < 4; ++mt) {
                unsigned addr = bufA + (a_row + mt * 16u) * ROWB + a_kh + kk * 32u;
                ldm_x4(addr, ah[mt]);
                ldm_x4(addr + MAT_BYTES, al[mt]);
            }
#pragma unroll
            for (int np = 0; np < 2; ++np) {
                unsigned addr = bufA + 2 * MAT_BYTES +
                                (b_row + np * 16u) * ROWB + b_kh + kk * 32u;
                ldm_x4(addr, bh[np]);
                ldm_x4(addr + MAT_BYTES, bl[np]);
            }
#pragma unroll
            for (int mt = 0; mt < 4; ++mt) {
#pragma unroll
                for (int nt = 0; nt < 4; ++nt) {
                    int np = nt >> 1, rp = (nt & 1) * 2;
                    float* acc = d[mt * 4 + nt];
                    mma16816(acc, ah[mt], bh[np][rp], bh[np][rp + 1]);
                    mma16816(acc, ah[mt], bl[np][rp], bl[np][rp + 1]);
                    mma16816(acc, al[mt], bh[np][rp], bh[np][rp + 1]);
                }
            }
        }
        __syncthreads();
        p ^= 1;
    }

    const int qr = lane >> 2;
    const int qc = (lane & 3) * 2;
#pragma unroll
    for (int mt = 0; mt < 4; ++mt) {
        int o0 = mbase + mt * 16 + qr;
        int o1 = o0 + 8;
        float bs0 = bias[o0], bs1 = bias[o1];
        float* row0 = Cp + ((long)b * COUT + o0) * HWSZ + j0 + nbase + qc;
        float* row1 = Cp + ((long)b * COUT + o1) * HWSZ + j0 + nbase + qc;
#pragma unroll
        for (int nt = 0; nt < 4; ++nt) {
            float* acc = d[mt * 4 + nt];
            float2 v0 = make_float2(fmaxf(acc[0] + bs0, 0.f), fmaxf(acc[1] + bs0, 0.f));
            float2 v1 = make_float2(fmaxf(acc[2] + bs1, 0.f), fmaxf(acc[3] + bs1, 0.f));
            *(float2*)(row0 + nt * 8) = v0;
            *(float2*)(row1 + nt * 8) = v1;
        }
    }
}

// ---------------- launch -----------------------------------------------------
extern "C" void kernel_launch(void* const* d_in, const int* in_sizes, int n_in,
                              void* d_out, int out_size)
{
    const float* x        = (const float*)d_in[0];
    const float* dc1_offw = (const float*)d_in[1];
    const float* dc1_offb = (const float*)d_in[2];
    const float* dc1_w    = (const float*)d_in[3];
    const float* bn1_g    = (const float*)d_in[4];
    const float* bn1_b    = (const float*)d_in[5];
    const float* bn1_m    = (const float*)d_in[6];
    const float* bn1_v    = (const float*)d_in[7];
    const float* dc2_offw = (const float*)d_in[8];
    const float* dc2_offb = (const float*)d_in[9];
    const float* dc2_w    = (const float*)d_in[10];
    const float* bn2_g    = (const float*)d_in[11];
    const float* bn2_b    = (const float*)d_in[12];
    const float* bn2_m    = (const float*)d_in[13];
    const float* bn2_v    = (const float*)d_in[14];
    const float* id_w     = (const float*)d_in[15];
    const float* id_b     = (const float*)d_in[16];
    const float* bn3_g    = (const float*)d_in[17];
    const float* bn3_b    = (const float*)d_in[18];
    const float* bn3_m    = (const float*)d_in[19];
    const float* bn3_v    = (const float*)d_in[20];
    float* out = (float*)d_out;

    cudaFuncSetAttribute(gemm_mma_kernel,
                         cudaFuncAttributeMaxDynamicSharedMemorySize, GEMM_SMEM);

    prep_scales<<<1, 128>>>(bn1_g, bn1_b, bn1_m, bn1_v,
                            bn2_g, bn2_b, bn2_m, bn2_v,
                            id_b, bn3_g, bn3_b, bn3_m, bn3_v);
    {
        int total = COUT * K1 + COUT * K2C + COUT * CIN;
        prep_weights<<<(total + 255) / 256, 256>>>(dc1_w, dc2_w, id_w);
    }

    const int RED_N = BATCH * 18 * HWSZ;

    // layer 1
    offset_partial_kernel<<<dim3(WW / 16, HH / 16, BATCH * (CIN / 16)), 128>>>(
        x, 0, dc1_offw, CIN);
    offset_reduce_kernel<<<(RED_N + 255) / 256, 256>>>(dc1_offb, CIN / 16);
    deform_sample_kernel<CIN, K1><<<dim3(HH, 9, BATCH), 128>>>(x, 0);
    gemm_mma_kernel<<<dim3(HWSZ / 128, BATCH), 256, GEMM_SMEM>>>(0, out);

    // layer 2
    offset_partial_kernel<<<dim3(WW / 16, HH / 16, BATCH * (COUT / 16)), 128>>>(
        x, 1, dc2_offw, COUT);
    offset_reduce_kernel<<<(RED_N + 255) / 256, 256>>>(dc2_offb, COUT / 16);
    deform_sample_kernel<COUT, K2><<<dim3(HH, 9, BATCH), 128>>>(x, 1);
    copy_x_tail_kernel<<<dim3(HWSZ / 128, BATCH), 128>>>(x);
    gemm_mma_kernel<<<dim3(HWSZ / 128, BATCH), 256, GEMM_SMEM>>>(1, out);
}